// round 6
// baseline (speedup 1.0000x reference)
#include <cuda_runtime.h>

#define NUM_B  4
#define SEQ    2048
#define DMODEL 1024
#define NH     16
#define DHEAD  64
#define MTOT   (NUM_B * SEQ)   // 8192

// Scratch (allocation-free rule: __device__ globals)
__device__ float g_q[(size_t)NUM_B * NH * SEQ * DHEAD];     // [B,H,S,Dh]
__device__ float g_k[(size_t)NUM_B * NH * SEQ * DHEAD];
__device__ float g_v[(size_t)NUM_B * NH * SEQ * DHEAD];
__device__ float g_attn[(size_t)NUM_B * SEQ * DMODEL];      // [B,S,D]

// ---------------------------------------------------------------------------
// Core 128x128x8 fp32 GEMM mainloop. 256 threads, 8x8 microtile per thread.
// C_tile = A[rowBase:+128, :K] * B[:K, colBase:+128]   (both row-major)
// ---------------------------------------------------------------------------
__device__ __forceinline__ void gemm_mainloop(
    const float* __restrict__ Ablk,   // A + rowBase*K
    const float* __restrict__ Bblk,   // B + colBase
    int K, int N,
    float (&acc)[8][8],
    float (*As)[128], float (*Bs)[128])
{
    const int t    = threadIdx.x;
    const int aRow = t >> 1, aCol = (t & 1) * 4;
    const int bRow = t >> 5, bCol = (t & 31) * 4;
    const int tRow = t >> 4, tCol = t & 15;

    for (int k0 = 0; k0 < K; k0 += 8) {
        float4 av = *(const float4*)(Ablk + (size_t)aRow * K + k0 + aCol);
        As[aCol + 0][aRow] = av.x;
        As[aCol + 1][aRow] = av.y;
        As[aCol + 2][aRow] = av.z;
        As[aCol + 3][aRow] = av.w;
        *(float4*)(&Bs[bRow][bCol]) =
            *(const float4*)(Bblk + (size_t)(k0 + bRow) * N + bCol);
        __syncthreads();
#pragma unroll
        for (int k = 0; k < 8; k++) {
            float ra[8], rb[8];
            *(float4*)&ra[0] = *(const float4*)&As[k][tRow * 8];
            *(float4*)&ra[4] = *(const float4*)&As[k][tRow * 8 + 4];
            *(float4*)&rb[0] = *(const float4*)&Bs[k][tCol * 8];
            *(float4*)&rb[4] = *(const float4*)&Bs[k][tCol * 8 + 4];
#pragma unroll
            for (int i = 0; i < 8; i++)
#pragma unroll
                for (int j = 0; j < 8; j++)
                    acc[i][j] += ra[i] * rb[j];
        }
        __syncthreads();
    }
}

// ---------------------------------------------------------------------------
// Kernel 1: fused QKV projection. grid = (N/128, M/128, 3), block = 256.
// Output scattered into [B,H,S,Dh] scratch layout.
// ---------------------------------------------------------------------------
__global__ __launch_bounds__(256)
void qkv_proj_kernel(const float* __restrict__ xq, const float* __restrict__ xk,
                     const float* __restrict__ xv,
                     const float* __restrict__ Wq, const float* __restrict__ Wk,
                     const float* __restrict__ Wv,
                     const float* __restrict__ bq, const float* __restrict__ bk,
                     const float* __restrict__ bv)
{
    __shared__ float As[8][128];
    __shared__ float Bs[8][128];

    const int sel = blockIdx.z;
    const float* X    = (sel == 0) ? xq : (sel == 1) ? xk : xv;
    const float* W    = (sel == 0) ? Wq : (sel == 1) ? Wk : Wv;
    const float* bias = (sel == 0) ? bq : (sel == 1) ? bk : bv;
    float* dst        = (sel == 0) ? g_q : (sel == 1) ? g_k : g_v;

    const int rowBase = blockIdx.y * 128;
    const int colBase = blockIdx.x * 128;

    float acc[8][8];
#pragma unroll
    for (int i = 0; i < 8; i++)
#pragma unroll
        for (int j = 0; j < 8; j++) acc[i][j] = 0.f;

    gemm_mainloop(X + (size_t)rowBase * DMODEL, W + colBase, DMODEL, DMODEL,
                  acc, As, Bs);

    const int t = threadIdx.x;
    const int tRow = t >> 4, tCol = t & 15;
#pragma unroll
    for (int i = 0; i < 8; i++) {
        const int r = rowBase + tRow * 8 + i;     // r = b*SEQ + s
        const int b = r / SEQ, s = r % SEQ;
#pragma unroll
        for (int j4 = 0; j4 < 8; j4 += 4) {
            const int n = colBase + tCol * 8 + j4; // n = h*DHEAD + d (j4 block stays in one head)
            const int h = n / DHEAD, d = n % DHEAD;
            float4 o;
            o.x = acc[i][j4 + 0] + bias[n + 0];
            o.y = acc[i][j4 + 1] + bias[n + 1];
            o.z = acc[i][j4 + 2] + bias[n + 2];
            o.w = acc[i][j4 + 3] + bias[n + 3];
            *(float4*)(dst + (((size_t)(b * NH + h) * SEQ + s) * DHEAD + d)) = o;
        }
    }
}

// ---------------------------------------------------------------------------
// Kernel 2: flash attention. grid = (SEQ/128, B*H), block = 256, dyn smem.
// Per block: 128 q-rows of one (b,h). Iterates 64-key tiles with online softmax.
// Microtile per thread: 8 q-rows (tRow) x 4 cols (tCol). Row stats reduced via
// 16-lane shfl (row groups are contiguous half-warps).
// ---------------------------------------------------------------------------
#define ATTN_SMEM_FLOATS (128*64 + 64*65 + 64*64 + 128*64)   // Qs, Kts(+pad), Vs, Ps

__global__ __launch_bounds__(256, 1)
void flash_attn_kernel(const int* __restrict__ mask)
{
    extern __shared__ float smem[];
    float* Qs  = smem;                 // [128][64] q-row major, pre-scaled
    float* Kts = Qs  + 128 * 64;       // [64][65]  d-major (transposed, padded)
    float* Vs  = Kts + 64 * 65;        // [64][64]  key-row major
    float* Ps  = Vs  + 64 * 64;        // [128][64] probs

    const int t    = threadIdx.x;
    const int tRow = t >> 4, tCol = t & 15;
    const int bh = blockIdx.y;
    const int b  = bh / NH, h = bh % NH;
    const int q0 = blockIdx.x * 128;

    const float* Qg = g_q + ((size_t)bh * SEQ + q0) * DHEAD;
    const float* Kg = g_k + (size_t)bh * SEQ * DHEAD;
    const float* Vg = g_v + (size_t)bh * SEQ * DHEAD;

    // Load Q tile, pre-scaled by 1/sqrt(Dh) = 0.125
    const float scale = 0.125f;
#pragma unroll
    for (int r = 0; r < 8; r++) {
        const int i = t + r * 256;                 // 2048 float4 total
        float4 v = ((const float4*)Qg)[i];
        v.x *= scale; v.y *= scale; v.z *= scale; v.w *= scale;
        ((float4*)Qs)[i] = v;
    }

    float Ot[8][4], mrow[8], lrow[8];
#pragma unroll
    for (int i = 0; i < 8; i++) {
        mrow[i] = -1e30f; lrow[i] = 0.f;
#pragma unroll
        for (int j = 0; j < 4; j++) Ot[i][j] = 0.f;
    }

    __syncthreads();

    for (int kt = 0; kt < SEQ / 64; kt++) {
        // Load K (transposed into d-major, pad 65 => conflict-free) and V
        const float* Kt0 = Kg + (size_t)kt * 64 * DHEAD;
        const float* Vt0 = Vg + (size_t)kt * 64 * DHEAD;
#pragma unroll
        for (int r = 0; r < 4; r++) {
            const int i   = t + r * 256;           // 1024 float4 total
            const int key = i >> 4;
            const int d4  = (i & 15) * 4;
            const float4 kv = ((const float4*)Kt0)[i];
            Kts[(d4 + 0) * 65 + key] = kv.x;
            Kts[(d4 + 1) * 65 + key] = kv.y;
            Kts[(d4 + 2) * 65 + key] = kv.z;
            Kts[(d4 + 3) * 65 + key] = kv.w;
            ((float4*)Vs)[i] = ((const float4*)Vt0)[i];
        }
        __syncthreads();

        // Scores: sc[i][j] = sum_d Qs[row][d] * K[col][d]
        float sc[8][4];
#pragma unroll
        for (int i = 0; i < 8; i++)
#pragma unroll
            for (int j = 0; j < 4; j++) sc[i][j] = 0.f;

#pragma unroll 8
        for (int d = 0; d < DHEAD; d++) {
            float kr[4];
#pragma unroll
            for (int j = 0; j < 4; j++) kr[j] = Kts[d * 65 + tCol * 4 + j];
#pragma unroll
            for (int i = 0; i < 8; i++) {
                const float qv = Qs[(tRow * 8 + i) * 64 + d];
#pragma unroll
                for (int j = 0; j < 4; j++) sc[i][j] += qv * kr[j];
            }
        }

        // Mask + online softmax
        const int kbase = kt * 64;
#pragma unroll
        for (int i = 0; i < 8; i++) {
            const int qrow = q0 + tRow * 8 + i;
            const int4 mv = *(const int4*)(mask +
                ((size_t)b * SEQ + qrow) * SEQ + kbase + tCol * 4);
            if (mv.x == 0) sc[i][0] = -1e9f;
            if (mv.y == 0) sc[i][1] = -1e9f;
            if (mv.z == 0) sc[i][2] = -1e9f;
            if (mv.w == 0) sc[i][3] = -1e9f;

            float mx = fmaxf(fmaxf(sc[i][0], sc[i][1]), fmaxf(sc[i][2], sc[i][3]));
#pragma unroll
            for (int off = 8; off > 0; off >>= 1)
                mx = fmaxf(mx, __shfl_xor_sync(0xffffffffu, mx, off));

            const float mnew = fmaxf(mrow[i], mx);
            const float corr = __expf(mrow[i] - mnew);
            float4 pv;
            pv.x = __expf(sc[i][0] - mnew);
            pv.y = __expf(sc[i][1] - mnew);
            pv.z = __expf(sc[i][2] - mnew);
            pv.w = __expf(sc[i][3] - mnew);
            float ssum = pv.x + pv.y + pv.z + pv.w;
#pragma unroll
            for (int off = 8; off > 0; off >>= 1)
                ssum += __shfl_xor_sync(0xffffffffu, ssum, off);

            lrow[i] = lrow[i] * corr + ssum;
            mrow[i] = mnew;
#pragma unroll
            for (int j = 0; j < 4; j++) Ot[i][j] *= corr;
            *(float4*)(Ps + (tRow * 8 + i) * 64 + tCol * 4) = pv;
        }
        __syncthreads();

        // O += P @ V
#pragma unroll 8
        for (int key = 0; key < 64; key++) {
            float vr[4];
            *(float4*)vr = *(const float4*)(Vs + key * 64 + tCol * 4);
#pragma unroll
            for (int i = 0; i < 8; i++) {
                const float p = Ps[(tRow * 8 + i) * 64 + key];
#pragma unroll
                for (int j = 0; j < 4; j++) Ot[i][j] += p * vr[j];
            }
        }
        __syncthreads();
    }

    // Normalize and write to [B,S,D] scratch (concat heads)
#pragma unroll
    for (int i = 0; i < 8; i++) {
        const int qrow = q0 + tRow * 8 + i;
        const float inv = 1.0f / lrow[i];
        float4 o;
        o.x = Ot[i][0] * inv; o.y = Ot[i][1] * inv;
        o.z = Ot[i][2] * inv; o.w = Ot[i][3] * inv;
        *(float4*)(g_attn + ((size_t)b * SEQ + qrow) * DMODEL + h * DHEAD + tCol * 4) = o;
    }
}

// ---------------------------------------------------------------------------
// Kernel 3: output projection. grid = (N/128, M/128), block = 256.
// ---------------------------------------------------------------------------
__global__ __launch_bounds__(256)
void out_proj_kernel(const float* __restrict__ Wo, const float* __restrict__ bo,
                     float* __restrict__ out)
{
    __shared__ float As[8][128];
    __shared__ float Bs[8][128];

    const int rowBase = blockIdx.y * 128;
    const int colBase = blockIdx.x * 128;

    float acc[8][8];
#pragma unroll
    for (int i = 0; i < 8; i++)
#pragma unroll
        for (int j = 0; j < 8; j++) acc[i][j] = 0.f;

    gemm_mainloop(g_attn + (size_t)rowBase * DMODEL, Wo + colBase, DMODEL, DMODEL,
                  acc, As, Bs);

    const int t = threadIdx.x;
    const int tRow = t >> 4, tCol = t & 15;
#pragma unroll
    for (int i = 0; i < 8; i++) {
        const int r = rowBase + tRow * 8 + i;
#pragma unroll
        for (int j4 = 0; j4 < 8; j4 += 4) {
            const int n = colBase + tCol * 8 + j4;
            float4 o;
            o.x = acc[i][j4 + 0] + bo[n + 0];
            o.y = acc[i][j4 + 1] + bo[n + 1];
            o.z = acc[i][j4 + 2] + bo[n + 2];
            o.w = acc[i][j4 + 3] + bo[n + 3];
            *(float4*)(out + (size_t)r * DMODEL + n) = o;
        }
    }
}

// ---------------------------------------------------------------------------
extern "C" void kernel_launch(void* const* d_in, const int* in_sizes, int n_in,
                              void* d_out, int out_size)
{
    (void)in_sizes; (void)n_in; (void)out_size;
    const float* q_in = (const float*)d_in[0];
    const float* k_in = (const float*)d_in[1];
    const float* v_in = (const float*)d_in[2];
    const int*   mask = (const int*)d_in[3];
    const float* Wq = (const float*)d_in[4];
    const float* bq = (const float*)d_in[5];
    const float* Wk = (const float*)d_in[6];
    const float* bk = (const float*)d_in[7];
    const float* Wv = (const float*)d_in[8];
    const float* bv = (const float*)d_in[9];
    const float* Wo = (const float*)d_in[10];
    const float* bo = (const float*)d_in[11];
    float* out = (float*)d_out;

    // Idempotent, not a stream op — safe under graph capture.
    cudaFuncSetAttribute(flash_attn_kernel,
                         cudaFuncAttributeMaxDynamicSharedMemorySize,
                         ATTN_SMEM_FLOATS * (int)sizeof(float));

    dim3 gP(DMODEL / 128, MTOT / 128, 3);
    qkv_proj_kernel<<<gP, 256>>>(q_in, k_in, v_in, Wq, Wk, Wv, bq, bk, bv);

    dim3 gA(SEQ / 128, NUM_B * NH);
    flash_attn_kernel<<<gA, 256, ATTN_SMEM_FLOATS * sizeof(float)>>>(mask);

    dim3 gO(DMODEL / 128, MTOT / 128);
    out_proj_kernel<<<gO, 256>>>(Wo, bo, out);
}